// round 7
// baseline (speedup 1.0000x reference)
#include <cuda_runtime.h>
#include <cuda_fp16.h>
#include <cstdint>

// ---------------------------------------------------------------------------
// FocDecoderRNN — cp.async TF32 engine with in-register A-fragment rounding
// (no pre-rounded copies of activations), fp16 gi buffers, L2-resident gi2
// chunking (8 cells/chunk), merged o1/o2 GEMM reading h directly from out.
// ---------------------------------------------------------------------------

#define BSZ  2048
#define MAXK 64
#define KCH  8      // gi2 chunk size (cells)

__device__ float  d_e1c [256 * 4096];             // tf32-rounded embed1_w
__device__ float  d_wi1c[768 * 256];              // tf32-rounded w_ih1
__device__ float  d_whhc[1536 * 256];             // tf32-rounded [whh1;whh2]
__device__ float  d_bhh [1536];
__device__ float  d_o1wc[64 * 256];               // tf32-rounded out1_w
__device__ float  d_o2wc[64 * 256];               // tf32-rounded out2_w
__device__ float  d_xp  [4 * BSZ * 256];
__device__ float  d_x1  [BSZ * 256];
__device__ float  d_gh12[(size_t)BSZ * 1536];
__device__ __half d_gi1h[BSZ * 768];
__device__ __half d_gi2h[(size_t)KCH * BSZ * 768];    // 25 MB, L2-resident
__device__ float  d_o   [(size_t)(MAXK + 1) * BSZ * 64];
__device__ float  d_w2p [768 * 64];
__device__ float  d_b2p [768];
__device__ int    d_cx[MAXK], d_cy[MAXK], d_cmap[64];

// ---------------------------------------------------------------------------
__device__ __forceinline__ uint32_t f2tf32(float x)
{
    uint32_t u;
    asm("cvt.rna.tf32.f32 %0, %1;" : "=r"(u) : "f"(x));
    return u;
}

__device__ __forceinline__ void mma_tf32(float c[4], const uint32_t a[4], const uint32_t b[2])
{
    asm volatile(
        "mma.sync.aligned.m16n8k8.row.col.f32.tf32.tf32.f32 "
        "{%0,%1,%2,%3},{%4,%5,%6,%7},{%8,%9},{%0,%1,%2,%3};\n"
        : "+f"(c[0]), "+f"(c[1]), "+f"(c[2]), "+f"(c[3])
        : "r"(a[0]), "r"(a[1]), "r"(a[2]), "r"(a[3]), "r"(b[0]), "r"(b[1]));
}

__device__ __forceinline__ void cp16(uint32_t smem_addr, const void* gptr)
{
    asm volatile("cp.async.cg.shared.global [%0], [%1], 16;"
                 :: "r"(smem_addr), "l"(gptr));
}

__device__ __forceinline__ float sigf(float x) { return 1.f / (1.f + __expf(-x)); }

// ---------------------------------------------------------------------------
__global__ void find_cells_kernel(const float* __restrict__ fa,
                                  int* __restrict__ cx, int* __restrict__ cy,
                                  int* __restrict__ cmap)
{
    if (threadIdx.x == 0 && blockIdx.x == 0) {
        for (int i = 0; i < 64; i++) cmap[i] = -1;
        int k = 0;
        for (int i = 0; i < 8; i++)
            for (int j = 0; j < 8; j++)
                if (fa[i * 8 + j] > 0.5f) { cx[k] = i; cy[k] = j; cmap[i * 8 + j] = k; k++; }
    }
}

__global__ void compose_w2_kernel(const float* __restrict__ wih2,
                                  const float* __restrict__ e2w,
                                  const float* __restrict__ e2b,
                                  const float* __restrict__ bih2,
                                  float* __restrict__ W2p, float* __restrict__ b2p)
{
    const int n = blockIdx.x;
    const int t = threadIdx.x;
    float s = 0.f;
    for (int c = 0; c < 256; c++)
        s += wih2[n * 256 + c] * e2w[c * 64 + t];
    W2p[n * 64 + t] = __uint_as_float(f2tf32(s));
    if (t == 0) {
        float sb = 0.f;
        for (int c = 0; c < 256; c++) sb += wih2[n * 256 + c] * e2b[c];
        b2p[n] = bih2[n] + sb;
    }
}

__global__ void cvt_tf32_kernel(const float* __restrict__ s, float* __restrict__ d, int n4)
{
    const int i = blockIdx.x * blockDim.x + threadIdx.x;
    if (i >= n4) return;
    const float4 v = reinterpret_cast<const float4*>(s)[i];
    uint4 u;
    u.x = f2tf32(v.x); u.y = f2tf32(v.y); u.z = f2tf32(v.z); u.w = f2tf32(v.w);
    reinterpret_cast<uint4*>(d)[i] = u;
}

__global__ void concat_whh_kernel(const float* __restrict__ w1, const float* __restrict__ w2,
                                  const float* __restrict__ b1, const float* __restrict__ b2,
                                  float* __restrict__ w12, float* __restrict__ b12)
{
    const int i = blockIdx.x * blockDim.x + threadIdx.x;
    if (i < 1536 * 64) {
        const int e = i * 4, row = e >> 8, col = e & 255;
        const float* src = (row < 768) ? (w1 + row * 256 + col) : (w2 + (row - 768) * 256 + col);
        const float4 v = *reinterpret_cast<const float4*>(src);
        uint4 u;
        u.x = f2tf32(v.x); u.y = f2tf32(v.y); u.z = f2tf32(v.z); u.w = f2tf32(v.w);
        reinterpret_cast<uint4*>(w12)[i] = u;
    }
    if (i < 1536) b12[i] = (i < 768) ? b1[i] : b2[i - 768];
}

// ---------------------------------------------------------------------------
// cp.async 3-stage TF32 GEMM-NT. Tile 128 x NT x 16.
//   A is RAW fp32; fragments are cvt.rna'd in-register (bit-identical to
//   pre-rounding). B must be pre-tf32-rounded (weights).
//   AMODE 0: normal A (lda, sAz).  AMODE 1: A = patch gather from x.
//   HOUT  0: fp32 C.              1: fp16 C.
//   OSEL  1: z>0 uses Bw2/bias2 (merged o1/o2 GEMM).
#define CAS  3
#define ROWU 20

template<int AMODE, int NT, int HOUT, int OSEL>
__global__ __launch_bounds__(256)
void gemm_ca(const float* __restrict__ A,
             const float* __restrict__ Bw, const float* __restrict__ Bw2,
             const float* __restrict__ bias, const float* __restrict__ bias2,
             void* __restrict__ Cv,
             int N, int K, int lda, int ldb,
             long long sAz, long long sBz, long long sCz,
             const int* __restrict__ cxs, const int* __restrict__ cys)
{
    constexpr int STG_A = 128 * ROWU;
    constexpr int STG_B = NT * ROWU;
    constexpr int WNW   = (NT == 128) ? 4 : 2;
    constexpr int MF    = (NT == 128) ? 4 : 2;

    extern __shared__ uint32_t sm[];
    const uint32_t smBase = (uint32_t)__cvta_generic_to_shared(sm);

    const int bm = blockIdx.y * 128;
    const int bn = blockIdx.x * NT;
    int cellBase = 0;
    if (AMODE == 1) cellBase = cxs[blockIdx.z] * 512 + cys[blockIdx.z] * 8;
    if (AMODE == 0) A += (long long)blockIdx.z * sAz;
    if (OSEL == 1 && blockIdx.z > 0) { Bw = Bw2; bias = bias2; }
    Bw += (long long)blockIdx.z * sBz;

    const int tid  = threadIdx.x;
    const int lane = tid & 31;
    const int wid  = tid >> 5;
    const int wm   = wid / WNW;
    const int wn   = wid % WNW;
    const int g    = lane >> 2;
    const int t    = lane & 3;
    const int lr   = tid >> 1;
    const int lk   = (tid & 1) * 8;
    const int br   = (NT == 128) ? (tid >> 1) : (tid >> 2);
    const int bc   = (NT == 128) ? (tid & 1) * 8 : (tid & 3) * 4;

    float acc[MF][4][4];
#pragma unroll
    for (int i = 0; i < MF; i++)
#pragma unroll
        for (int j = 0; j < 4; j++)
#pragma unroll
            for (int q = 0; q < 4; q++) acc[i][j][q] = 0.f;

    auto issue = [&](int stg, int k0) {
        const float* ap;
        if (AMODE == 0) ap = A + (long long)(bm + lr) * lda + k0 + lk;
        else { const int tt = k0 + lk;
               ap = A + (long long)(bm + lr) * 4096 + cellBase + ((tt >> 3) << 6); }
        const uint32_t da = smBase + 4u * (stg * STG_A + lr * ROWU + lk);
        cp16(da,      ap);
        cp16(da + 16, ap + 4);
        const float* bp = Bw + (long long)(bn + br) * ldb + k0 + bc;
        const uint32_t db = smBase + 4u * (CAS * STG_A + stg * STG_B + br * ROWU + bc);
        cp16(db, bp);
        if (NT == 128) cp16(db + 16, bp + 4);
    };

    const int nIter = K >> 4;
#pragma unroll
    for (int s = 0; s < CAS - 1; s++) {
        if (s < nIter) issue(s, s * 16);
        asm volatile("cp.async.commit_group;");
    }

    for (int it = 0; it < nIter; it++) {
        const int cur = it % CAS;
        asm volatile("cp.async.wait_group %0;" :: "n"(CAS - 2));
        __syncthreads();

        const uint32_t* Ab = sm + cur * STG_A;
        const uint32_t* Bb = sm + CAS * STG_A + cur * STG_B;
#pragma unroll
        for (int kk = 0; kk < 16; kk += 8) {
            uint32_t af[MF][4], bf[4][2];
#pragma unroll
            for (int i = 0; i < MF; i++) {
                const int m = wm * (MF * 16) + i * 16;
                af[i][0] = f2tf32(__uint_as_float(Ab[(m + g) * ROWU + kk + t]));
                af[i][1] = f2tf32(__uint_as_float(Ab[(m + 8 + g) * ROWU + kk + t]));
                af[i][2] = f2tf32(__uint_as_float(Ab[(m + g) * ROWU + kk + t + 4]));
                af[i][3] = f2tf32(__uint_as_float(Ab[(m + 8 + g) * ROWU + kk + t + 4]));
            }
#pragma unroll
            for (int j = 0; j < 4; j++) {
                const int n = wn * 32 + j * 8;
                bf[j][0] = Bb[(n + g) * ROWU + kk + t];
                bf[j][1] = Bb[(n + g) * ROWU + kk + t + 4];
            }
#pragma unroll
            for (int i = 0; i < MF; i++)
#pragma unroll
                for (int j = 0; j < 4; j++) mma_tf32(acc[i][j], af[i], bf[j]);
        }
        const int nk = it + CAS - 1;
        if (nk < nIter) issue(nk % CAS, nk * 16);
        asm volatile("cp.async.commit_group;");
    }

    // ---- epilogue ----
    float* Cf = (float*)Cv;
    __half* Ch = (__half*)Cv;
#pragma unroll
    for (int i = 0; i < MF; i++) {
        const int row0 = bm + wm * (MF * 16) + i * 16 + g;
#pragma unroll
        for (int j = 0; j < 4; j++) {
            const int col = bn + wn * 32 + j * 8 + 2 * t;
            float bz0 = 0.f, bz1 = 0.f;
            if (bias) { bz0 = __ldg(&bias[col]); bz1 = __ldg(&bias[col + 1]); }
            const float v0 = acc[i][j][0] + bz0, v1 = acc[i][j][1] + bz1;
            const float v2 = acc[i][j][2] + bz0, v3 = acc[i][j][3] + bz1;
            if (HOUT == 0) {
                float* C = Cf + (long long)blockIdx.z * sCz;
                *reinterpret_cast<float2*>(&C[(long long)row0 * N + col]) = make_float2(v0, v1);
                *reinterpret_cast<float2*>(&C[(long long)(row0 + 8) * N + col]) = make_float2(v2, v3);
            } else {
                __half* C = Ch + (long long)blockIdx.z * sCz;
                *reinterpret_cast<__half2*>(&C[(long long)row0 * N + col]) =
                    __floats2half2_rn(v0, v1);
                *reinterpret_cast<__half2*>(&C[(long long)(row0 + 8) * N + col]) =
                    __floats2half2_rn(v2, v3);
            }
        }
    }
}

// ---------------------------------------------------------------------------
__global__ void reduce_x1_kernel(const float* __restrict__ P, const float* __restrict__ bias,
                                 float* __restrict__ x1, int n4)
{
    const int idx = blockIdx.x * blockDim.x + threadIdx.x;
    if (idx >= n4) return;
    const float4 p0 = *reinterpret_cast<const float4*>(P + (size_t)0 * BSZ * 256 + idx * 4);
    const float4 p1 = *reinterpret_cast<const float4*>(P + (size_t)1 * BSZ * 256 + idx * 4);
    const float4 p2 = *reinterpret_cast<const float4*>(P + (size_t)2 * BSZ * 256 + idx * 4);
    const float4 p3 = *reinterpret_cast<const float4*>(P + (size_t)3 * BSZ * 256 + idx * 4);
    const int j0 = (idx * 4) & 255;
    const float4 b = *reinterpret_cast<const float4*>(bias + j0);
    float4 r;
    r.x = p0.x + p1.x + p2.x + p3.x + b.x;
    r.y = p0.y + p1.y + p2.y + p3.y + b.y;
    r.z = p0.z + p1.z + p2.z + p3.z + b.z;
    r.w = p0.w + p1.w + p2.w + p3.w + b.w;
    *reinterpret_cast<float4*>(x1 + idx * 4) = r;
}

// ---------------------------------------------------------------------------
// GRU from fp16 gi; writes exact h only.
__global__ void gru_elem_h_kernel(const __half* __restrict__ gi, const float* __restrict__ gh,
                                  const float* __restrict__ h0, float* __restrict__ hout,
                                  int n4, long long giZ, long long hoZ, int ghStride)
{
    const long long z = blockIdx.z;
    const int idx = blockIdx.x * blockDim.x + threadIdx.x;   // over B*64
    if (idx >= n4) return;
    const int b = idx >> 6;
    const int j = (idx & 63) * 4;
    const __half* g = gi + z * giZ + (long long)b * 768;
    const float* q  = gh + (long long)b * ghStride;

    const float2 ir01 = __half22float2(*reinterpret_cast<const __half2*>(g + j));
    const float2 ir23 = __half22float2(*reinterpret_cast<const __half2*>(g + j + 2));
    const float2 iz01 = __half22float2(*reinterpret_cast<const __half2*>(g + 256 + j));
    const float2 iz23 = __half22float2(*reinterpret_cast<const __half2*>(g + 256 + j + 2));
    const float2 in01 = __half22float2(*reinterpret_cast<const __half2*>(g + 512 + j));
    const float2 in23 = __half22float2(*reinterpret_cast<const __half2*>(g + 512 + j + 2));
    const float4 hr = *reinterpret_cast<const float4*>(q + j);
    const float4 hz = *reinterpret_cast<const float4*>(q + 256 + j);
    const float4 hn = *reinterpret_cast<const float4*>(q + 512 + j);
    const float4 hh = *reinterpret_cast<const float4*>(h0 + (long long)b * 256 + j);

    float4 r;
    { const float rr = sigf(ir01.x + hr.x), zz = sigf(iz01.x + hz.x);
      r.x = (1.f - zz) * tanhf(in01.x + rr * hn.x) + zz * hh.x; }
    { const float rr = sigf(ir01.y + hr.y), zz = sigf(iz01.y + hz.y);
      r.y = (1.f - zz) * tanhf(in01.y + rr * hn.y) + zz * hh.y; }
    { const float rr = sigf(ir23.x + hr.z), zz = sigf(iz23.x + hz.z);
      r.z = (1.f - zz) * tanhf(in23.x + rr * hn.z) + zz * hh.z; }
    { const float rr = sigf(ir23.y + hr.w), zz = sigf(iz23.y + hz.w);
      r.w = (1.f - zz) * tanhf(in23.y + rr * hn.w) + zz * hh.w; }

    *reinterpret_cast<float4*>(hout + z * hoZ + (long long)b * 256 + j) = r;
}

// ---------------------------------------------------------------------------
__global__ void assemble_y_kernel(const float* __restrict__ o1, const float* __restrict__ o2,
                                  const int* __restrict__ cmap, float* __restrict__ y, int n4)
{
    const int idx = blockIdx.x * blockDim.x + threadIdx.x;   // over B*1024
    if (idx >= n4) return;
    const int b   = idx >> 10;
    const int rem = idx & 1023;
    const int i   = rem >> 4;
    const int j0  = (rem & 15) * 4;
    const float v = __ldg(&o1[b * 64 + i]);
    float4 r = make_float4(v, v, v, v);
    const int k = cmap[(i >> 3) * 8 + (j0 >> 3)];
    if (k >= 0) {
        const int t = (i & 7) * 8 + (j0 & 7);
        const float4 a = *reinterpret_cast<const float4*>(o2 + ((long long)k * BSZ + b) * 64 + t);
        r.x += a.x; r.y += a.y; r.z += a.z; r.w += a.w;
    }
    *reinterpret_cast<float4*>(y + (long long)idx * 4) = r;
}

// ---------------------------------------------------------------------------
extern "C" void kernel_launch(void* const* d_in, const int* in_sizes, int n_in,
                              void* d_out, int out_size)
{
    const float* x    = (const float*)d_in[0];
    const float* h    = (const float*)d_in[1];
    const float* fa   = (const float*)d_in[2];
    const float* e1w  = (const float*)d_in[3];
    const float* e1b  = (const float*)d_in[4];
    const float* wih1 = (const float*)d_in[5];
    const float* whh1 = (const float*)d_in[6];
    const float* bih1 = (const float*)d_in[7];
    const float* bhh1 = (const float*)d_in[8];
    const float* o1w  = (const float*)d_in[9];
    const float* o1b  = (const float*)d_in[10];
    const float* e2w  = (const float*)d_in[11];
    const float* e2b  = (const float*)d_in[12];
    const float* wih2 = (const float*)d_in[13];
    const float* whh2 = (const float*)d_in[14];
    const float* bih2 = (const float*)d_in[15];
    const float* bhh2 = (const float*)d_in[16];
    const float* o2w  = (const float*)d_in[17];
    const float* o2b  = (const float*)d_in[18];
    float* out = (float*)d_out;

    const int B = in_sizes[0] / 4096;                  // 2048
    const long long YOFF = (long long)B * 4096;
    int Kc = (int)(((long long)out_size - YOFF) / ((long long)B * 256)) - 1;
    if (Kc < 0) Kc = 0;
    if (Kc > MAXK) Kc = MAXK;

    float *p_e1c, *p_wi1c, *p_whhc, *p_bhh, *p_o1wc, *p_o2wc,
          *p_xp, *p_x1, *p_gh12, *p_o, *p_w2p, *p_b2p;
    __half *p_gi1h, *p_gi2h;
    int *p_cx, *p_cy, *p_cmap;
    cudaGetSymbolAddress((void**)&p_e1c,  d_e1c);
    cudaGetSymbolAddress((void**)&p_wi1c, d_wi1c);
    cudaGetSymbolAddress((void**)&p_whhc, d_whhc);
    cudaGetSymbolAddress((void**)&p_bhh,  d_bhh);
    cudaGetSymbolAddress((void**)&p_o1wc, d_o1wc);
    cudaGetSymbolAddress((void**)&p_o2wc, d_o2wc);
    cudaGetSymbolAddress((void**)&p_xp,   d_xp);
    cudaGetSymbolAddress((void**)&p_x1,   d_x1);
    cudaGetSymbolAddress((void**)&p_gh12, d_gh12);
    cudaGetSymbolAddress((void**)&p_gi1h, d_gi1h);
    cudaGetSymbolAddress((void**)&p_gi2h, d_gi2h);
    cudaGetSymbolAddress((void**)&p_o,    d_o);
    cudaGetSymbolAddress((void**)&p_w2p,  d_w2p);
    cudaGetSymbolAddress((void**)&p_b2p,  d_b2p);
    cudaGetSymbolAddress((void**)&p_cx,   d_cx);
    cudaGetSymbolAddress((void**)&p_cy,   d_cy);
    cudaGetSymbolAddress((void**)&p_cmap, d_cmap);

    const int SMB128 = 61440;                // 3*(128+128)*20*4
    const int SMB64  = 46080;                // 3*(128+64)*20*4
    cudaFuncSetAttribute((const void*)gemm_ca<0, 128, 0, 0>, cudaFuncAttributeMaxDynamicSharedMemorySize, SMB128);
    cudaFuncSetAttribute((const void*)gemm_ca<0, 128, 1, 0>, cudaFuncAttributeMaxDynamicSharedMemorySize, SMB128);
    cudaFuncSetAttribute((const void*)gemm_ca<1, 128, 1, 0>, cudaFuncAttributeMaxDynamicSharedMemorySize, SMB128);
    cudaFuncSetAttribute((const void*)gemm_ca<0, 64, 0, 1>,  cudaFuncAttributeMaxDynamicSharedMemorySize, SMB64);

    float* yh0 = out + YOFF;                           // h slots (contiguous)
    float* yh2 = out + YOFF + (long long)B * 256;

    find_cells_kernel<<<1, 32>>>(fa, p_cx, p_cy, p_cmap);
    compose_w2_kernel<<<768, 64>>>(wih2, e2w, e2b, bih2, p_w2p, p_b2p);

    // pre-round B-side weights only (small)
    cvt_tf32_kernel<<<(256 * 1024 + 255) / 256, 256>>>(e1w, p_e1c, 256 * 1024);
    cvt_tf32_kernel<<<(768 * 64 + 255) / 256, 256>>>(wih1, p_wi1c, 768 * 64);
    cvt_tf32_kernel<<<(64 * 64 + 255) / 256, 256>>>(o1w, p_o1wc, 64 * 64);
    cvt_tf32_kernel<<<(64 * 64 + 255) / 256, 256>>>(o2w, p_o2wc, 64 * 64);
    concat_whh_kernel<<<(1536 * 64 + 255) / 256, 256>>>(whh1, whh2, bhh1, bhh2, p_whhc, p_bhh);

    // x1 split-K=4 partials (A = raw x; fragment cvt) + reduce
    gemm_ca<0, 128, 0, 0><<<dim3(2, B / 128, 4), 256, SMB128>>>(
        x, p_e1c, nullptr, nullptr, nullptr, p_xp,
        256, 1024, 4096, 4096, 1024, 1024, (long long)B * 256, nullptr, nullptr);
    reduce_x1_kernel<<<(B * 64 + 255) / 256, 256>>>(p_xp, e1b, p_x1, B * 64);

    // gh12 = h @ [whh1;whh2]^T + [bhh1;bhh2]  (A = raw h)
    gemm_ca<0, 128, 0, 0><<<dim3(12, B / 128), 256, SMB128>>>(
        h, p_whhc, nullptr, p_bhh, nullptr, p_gh12,
        1536, 256, 256, 256, 0, 0, 0, nullptr, nullptr);

    // gi1 = x1 @ wih1^T + bih1 -> fp16
    gemm_ca<0, 128, 1, 0><<<dim3(6, B / 128), 256, SMB128>>>(
        p_x1, p_wi1c, nullptr, bih1, nullptr, p_gi1h,
        768, 256, 256, 256, 0, 0, 0, nullptr, nullptr);

    // h1 -> out y_h[0]
    gru_elem_h_kernel<<<dim3((B * 64 + 255) / 256, 1, 1), 256>>>(
        p_gi1h, p_gh12, h, yh0, B * 64, 0, 0, 1536);

    // gi2/h2 in L2-resident chunks of KCH cells
    for (int c0 = 0; c0 < Kc; c0 += KCH) {
        const int kn = (Kc - c0 < KCH) ? (Kc - c0) : KCH;
        gemm_ca<1, 128, 1, 0><<<dim3(6, B / 128, kn), 256, SMB128>>>(
            x, p_w2p, nullptr, p_b2p, nullptr, p_gi2h,
            768, 64, 64, 64, 0, 0, (long long)B * 768, p_cx + c0, p_cy + c0);
        gru_elem_h_kernel<<<dim3((B * 64 + 255) / 256, 1, kn), 256>>>(
            p_gi2h, p_gh12 + 768, h, yh2 + (long long)c0 * B * 256,
            B * 64, (long long)B * 768, (long long)B * 256, 1536);
    }

    // merged o GEMM: A = exact h slots in out (fragment cvt); z=0 o1w, z>0 o2w
    gemm_ca<0, 64, 0, 1><<<dim3(1, B / 128, Kc + 1), 256, SMB64>>>(
        yh0, p_o1wc, p_o2wc, o1b, o2b, p_o,
        64, 256, 256, 256, (long long)B * 256, 0, (long long)B * 64, nullptr, nullptr);

    // y = bcast(o1) + scatter(o2)
    assemble_y_kernel<<<(B * 1024 + 255) / 256, 256>>>(p_o, p_o + (long long)B * 64,
                                                       p_cmap, out, B * 1024);
}

// round 8
// speedup vs baseline: 1.4070x; 1.4070x over previous
#include <cuda_runtime.h>
#include <cuda_fp16.h>
#include <cstdint>

// ---------------------------------------------------------------------------
// FocDecoderRNN — fp16 tensor-core engine (m16n8k16, fp32 accumulate).
// R6 structure: pre-converted fp16 operand copies, fp16 gi buffers, GRU
// dual-write (exact fp32 h -> out, fp16 h -> scratch for o-GEMM), merged
// o1/o2 GEMM, single-pass y assembly. No per-fragment conversion, no
// chunking (lessons R4/R7).
// ---------------------------------------------------------------------------

#define BSZ  2048
#define MAXK 64

__device__ __half d_xh  [(size_t)BSZ * 4096];      // fp16 x
__device__ __half d_hh  [BSZ * 256];               // fp16 h
__device__ __half d_e1h [256 * 4096];              // fp16 embed1_w
__device__ __half d_wi1h[768 * 256];               // fp16 w_ih1
__device__ __half d_whhh[1536 * 256];              // fp16 [whh1;whh2]
__device__ float  d_bhh [1536];
__device__ __half d_o1wh[64 * 256];
__device__ __half d_o2wh[64 * 256];
__device__ float  d_xp  [4 * BSZ * 256];
__device__ __half d_x1h [BSZ * 256];
__device__ float  d_gh12[(size_t)BSZ * 1536];
__device__ __half d_gi1h[BSZ * 768];
__device__ __half d_gi2h[(size_t)MAXK * BSZ * 768];
__device__ __half d_hh16[(size_t)(MAXK + 1) * BSZ * 256]; // fp16 h slots
__device__ float  d_o   [(size_t)(MAXK + 1) * BSZ * 64];
__device__ __half d_w2ph[768 * 64];
__device__ float  d_b2p [768];
__device__ int    d_cx[MAXK], d_cy[MAXK], d_cmap[64];

// ---------------------------------------------------------------------------
__device__ __forceinline__ void mma_f16(float c[4], const uint32_t a[4], const uint32_t b[2])
{
    asm volatile(
        "mma.sync.aligned.m16n8k16.row.col.f32.f16.f16.f32 "
        "{%0,%1,%2,%3},{%4,%5,%6,%7},{%8,%9},{%0,%1,%2,%3};\n"
        : "+f"(c[0]), "+f"(c[1]), "+f"(c[2]), "+f"(c[3])
        : "r"(a[0]), "r"(a[1]), "r"(a[2]), "r"(a[3]), "r"(b[0]), "r"(b[1]));
}

__device__ __forceinline__ void cp16(uint32_t smem_addr, const void* gptr)
{
    asm volatile("cp.async.cg.shared.global [%0], [%1], 16;"
                 :: "r"(smem_addr), "l"(gptr));
}

__device__ __forceinline__ float sigf(float x) { return 1.f / (1.f + __expf(-x)); }

// ---------------------------------------------------------------------------
__global__ void find_cells_kernel(const float* __restrict__ fa,
                                  int* __restrict__ cx, int* __restrict__ cy,
                                  int* __restrict__ cmap)
{
    if (threadIdx.x == 0 && blockIdx.x == 0) {
        for (int i = 0; i < 64; i++) cmap[i] = -1;
        int k = 0;
        for (int i = 0; i < 8; i++)
            for (int j = 0; j < 8; j++)
                if (fa[i * 8 + j] > 0.5f) { cx[k] = i; cy[k] = j; cmap[i * 8 + j] = k; k++; }
    }
}

__global__ void compose_w2_kernel(const float* __restrict__ wih2,
                                  const float* __restrict__ e2w,
                                  const float* __restrict__ e2b,
                                  const float* __restrict__ bih2,
                                  __half* __restrict__ W2p, float* __restrict__ b2p)
{
    const int n = blockIdx.x;
    const int t = threadIdx.x;
    float s = 0.f;
    for (int c = 0; c < 256; c++)
        s += wih2[n * 256 + c] * e2w[c * 64 + t];
    W2p[n * 64 + t] = __float2half_rn(s);
    if (t == 0) {
        float sb = 0.f;
        for (int c = 0; c < 256; c++) sb += wih2[n * 256 + c] * e2b[c];
        b2p[n] = bih2[n] + sb;
    }
}

__global__ void cvt_f16_kernel(const float* __restrict__ s, __half* __restrict__ d, int n4)
{
    const int i = blockIdx.x * blockDim.x + threadIdx.x;
    if (i >= n4) return;
    const float4 v = reinterpret_cast<const float4*>(s)[i];
    reinterpret_cast<__half2*>(d)[i * 2]     = __floats2half2_rn(v.x, v.y);
    reinterpret_cast<__half2*>(d)[i * 2 + 1] = __floats2half2_rn(v.z, v.w);
}

__global__ void concat_whh_kernel(const float* __restrict__ w1, const float* __restrict__ w2,
                                  const float* __restrict__ b1, const float* __restrict__ b2,
                                  __half* __restrict__ w12, float* __restrict__ b12)
{
    const int i = blockIdx.x * blockDim.x + threadIdx.x;
    if (i < 1536 * 64) {
        const int e = i * 4, row = e >> 8, col = e & 255;
        const float* src = (row < 768) ? (w1 + row * 256 + col) : (w2 + (row - 768) * 256 + col);
        const float4 v = *reinterpret_cast<const float4*>(src);
        reinterpret_cast<__half2*>(w12)[i * 2]     = __floats2half2_rn(v.x, v.y);
        reinterpret_cast<__half2*>(w12)[i * 2 + 1] = __floats2half2_rn(v.z, v.w);
    }
    if (i < 1536) b12[i] = (i < 768) ? b1[i] : b2[i - 768];
}

// ---------------------------------------------------------------------------
// cp.async 3-stage FP16 GEMM-NT: C[z](128-tile, NT-tile) = A @ Bw^T (+bias)
// K-slab 32, mma m16n8k16, fp32 accumulators. Rows padded to 40 halves
// (16B-aligned cp.async dests; stride-20-word fragment reads = bank-clean).
//   AMODE 0: normal A.  AMODE 1: A = patch gather from xh.
//   HOUT  0: fp32 C.    1: fp16 C.
//   OSEL  1: z>0 uses Bw2/bias2 (merged o1/o2).
#define CAS  3
#define ROWH 40

template<int AMODE, int NT, int HOUT, int OSEL>
__global__ __launch_bounds__(256)
void gemm_hf(const __half* __restrict__ A,
             const __half* __restrict__ Bw, const __half* __restrict__ Bw2,
             const float* __restrict__ bias, const float* __restrict__ bias2,
             void* __restrict__ Cv,
             int N, int K, int lda, int ldb,
             long long sAz, long long sBz, long long sCz,
             const int* __restrict__ cxs, const int* __restrict__ cys)
{
    constexpr int STG_A = 128 * ROWH;       // halves per A stage
    constexpr int STG_B = NT * ROWH;
    constexpr int WNW   = (NT == 128) ? 4 : 2;
    constexpr int MF    = (NT == 128) ? 4 : 2;

    extern __shared__ __half smh[];
    const uint32_t smBase = (uint32_t)__cvta_generic_to_shared(smh);

    const int bm = blockIdx.y * 128;
    const int bn = blockIdx.x * NT;
    int cellBase = 0;
    if (AMODE == 1) cellBase = cxs[blockIdx.z] * 512 + cys[blockIdx.z] * 8;
    if (AMODE == 0) A += (long long)blockIdx.z * sAz;
    if (OSEL == 1 && blockIdx.z > 0) { Bw = Bw2; bias = bias2; }
    Bw += (long long)blockIdx.z * sBz;

    const int tid  = threadIdx.x;
    const int lane = tid & 31;
    const int wid  = tid >> 5;
    const int wm   = wid / WNW;
    const int wn   = wid % WNW;
    const int g    = lane >> 2;
    const int t2   = (lane & 3) * 2;       // half-offset within k16
    const int lr   = tid >> 1;             // A row 0..127
    const int lk   = (tid & 1) * 16;       // A half-offset 0/16
    const int br   = (NT == 128) ? (tid >> 1) : (tid >> 2);
    const int bc   = (NT == 128) ? (tid & 1) * 16 : (tid & 3) * 8;

    float acc[MF][4][4];
#pragma unroll
    for (int i = 0; i < MF; i++)
#pragma unroll
        for (int j = 0; j < 4; j++)
#pragma unroll
            for (int q = 0; q < 4; q++) acc[i][j][q] = 0.f;

    auto issue = [&](int stg, int k0) {
        const __half *ap0, *ap1;
        if (AMODE == 0) {
            ap0 = A + (long long)(bm + lr) * lda + k0 + lk;
            ap1 = ap0 + 8;
        } else {
            const int tt = k0 + lk;        // multiple of 8
            const __half* base = A + (long long)(bm + lr) * 4096 + cellBase;
            ap0 = base + ((tt >> 3) << 6);
            ap1 = base + (((tt + 8) >> 3) << 6);
        }
        const uint32_t da = smBase + 2u * (stg * STG_A + lr * ROWH + lk);
        cp16(da,      ap0);
        cp16(da + 16, ap1);
        const __half* bp = Bw + (long long)(bn + br) * ldb + k0 + bc;
        const uint32_t db = smBase + 2u * (CAS * STG_A + stg * STG_B + br * ROWH + bc);
        cp16(db, bp);
        if (NT == 128) cp16(db + 16, bp + 8);
    };

    const int nIter = K >> 5;              // slab 32
#pragma unroll
    for (int s = 0; s < CAS - 1; s++) {
        if (s < nIter) issue(s, s * 32);
        asm volatile("cp.async.commit_group;");
    }

    for (int it = 0; it < nIter; it++) {
        const int cur = it % CAS;
        asm volatile("cp.async.wait_group %0;" :: "n"(CAS - 2));
        __syncthreads();

        const __half* Ab = smh + cur * STG_A;
        const __half* Bb = smh + CAS * STG_A + cur * STG_B;
#pragma unroll
        for (int kk = 0; kk < 32; kk += 16) {
            uint32_t af[MF][4], bf[4][2];
#pragma unroll
            for (int i = 0; i < MF; i++) {
                const int m = wm * (MF * 16) + i * 16;
                af[i][0] = *reinterpret_cast<const uint32_t*>(Ab + (m + g) * ROWH + kk + t2);
                af[i][1] = *reinterpret_cast<const uint32_t*>(Ab + (m + 8 + g) * ROWH + kk + t2);
                af[i][2] = *reinterpret_cast<const uint32_t*>(Ab + (m + g) * ROWH + kk + t2 + 8);
                af[i][3] = *reinterpret_cast<const uint32_t*>(Ab + (m + 8 + g) * ROWH + kk + t2 + 8);
            }
#pragma unroll
            for (int j = 0; j < 4; j++) {
                const int n = wn * 32 + j * 8;
                bf[j][0] = *reinterpret_cast<const uint32_t*>(Bb + (n + g) * ROWH + kk + t2);
                bf[j][1] = *reinterpret_cast<const uint32_t*>(Bb + (n + g) * ROWH + kk + t2 + 8);
            }
#pragma unroll
            for (int i = 0; i < MF; i++)
#pragma unroll
                for (int j = 0; j < 4; j++) mma_f16(acc[i][j], af[i], bf[j]);
        }
        const int nk = it + CAS - 1;
        if (nk < nIter) issue(nk % CAS, nk * 32);
        asm volatile("cp.async.commit_group;");
    }

    // ---- epilogue ----
    float* Cf = (float*)Cv;
    __half* Ch = (__half*)Cv;
#pragma unroll
    for (int i = 0; i < MF; i++) {
        const int row0 = bm + wm * (MF * 16) + i * 16 + g;
#pragma unroll
        for (int j = 0; j < 4; j++) {
            const int col = bn + wn * 32 + j * 8 + t2;
            float bz0 = 0.f, bz1 = 0.f;
            if (bias) { bz0 = __ldg(&bias[col]); bz1 = __ldg(&bias[col + 1]); }
            const float v0 = acc[i][j][0] + bz0, v1 = acc[i][j][1] + bz1;
            const float v2 = acc[i][j][2] + bz0, v3 = acc[i][j][3] + bz1;
            if (HOUT == 0) {
                float* C = Cf + (long long)blockIdx.z * sCz;
                *reinterpret_cast<float2*>(&C[(long long)row0 * N + col]) = make_float2(v0, v1);
                *reinterpret_cast<float2*>(&C[(long long)(row0 + 8) * N + col]) = make_float2(v2, v3);
            } else {
                __half* C = Ch + (long long)blockIdx.z * sCz;
                *reinterpret_cast<__half2*>(&C[(long long)row0 * N + col]) =
                    __floats2half2_rn(v0, v1);
                *reinterpret_cast<__half2*>(&C[(long long)(row0 + 8) * N + col]) =
                    __floats2half2_rn(v2, v3);
            }
        }
    }
}

// ---------------------------------------------------------------------------
// x1 = sum of 4 split-K partials + bias -> fp16
__global__ void reduce_x1_kernel(const float* __restrict__ P, const float* __restrict__ bias,
                                 __half* __restrict__ x1, int n4)
{
    const int idx = blockIdx.x * blockDim.x + threadIdx.x;
    if (idx >= n4) return;
    const float4 p0 = *reinterpret_cast<const float4*>(P + (size_t)0 * BSZ * 256 + idx * 4);
    const float4 p1 = *reinterpret_cast<const float4*>(P + (size_t)1 * BSZ * 256 + idx * 4);
    const float4 p2 = *reinterpret_cast<const float4*>(P + (size_t)2 * BSZ * 256 + idx * 4);
    const float4 p3 = *reinterpret_cast<const float4*>(P + (size_t)3 * BSZ * 256 + idx * 4);
    const int j0 = (idx * 4) & 255;
    const float4 b = *reinterpret_cast<const float4*>(bias + j0);
    reinterpret_cast<__half2*>(x1)[idx * 2] =
        __floats2half2_rn(p0.x + p1.x + p2.x + p3.x + b.x,
                          p0.y + p1.y + p2.y + p3.y + b.y);
    reinterpret_cast<__half2*>(x1)[idx * 2 + 1] =
        __floats2half2_rn(p0.z + p1.z + p2.z + p3.z + b.z,
                          p0.w + p1.w + p2.w + p3.w + b.w);
}

// ---------------------------------------------------------------------------
// GRU from fp16 gi. Dual write: exact fp32 h -> hout, fp16 h -> h16.
__global__ void gru_elem_h_kernel(const __half* __restrict__ gi, const float* __restrict__ gh,
                                  const float* __restrict__ h0,
                                  float* __restrict__ hout, __half* __restrict__ h16,
                                  int n4, long long giZ, long long hoZ, int ghStride)
{
    const long long z = blockIdx.z;
    const int idx = blockIdx.x * blockDim.x + threadIdx.x;   // over B*64
    if (idx >= n4) return;
    const int b = idx >> 6;
    const int j = (idx & 63) * 4;
    const __half* g = gi + z * giZ + (long long)b * 768;
    const float* q  = gh + (long long)b * ghStride;

    const float2 ir01 = __half22float2(*reinterpret_cast<const __half2*>(g + j));
    const float2 ir23 = __half22float2(*reinterpret_cast<const __half2*>(g + j + 2));
    const float2 iz01 = __half22float2(*reinterpret_cast<const __half2*>(g + 256 + j));
    const float2 iz23 = __half22float2(*reinterpret_cast<const __half2*>(g + 256 + j + 2));
    const float2 in01 = __half22float2(*reinterpret_cast<const __half2*>(g + 512 + j));
    const float2 in23 = __half22float2(*reinterpret_cast<const __half2*>(g + 512 + j + 2));
    const float4 hr = *reinterpret_cast<const float4*>(q + j);
    const float4 hz = *reinterpret_cast<const float4*>(q + 256 + j);
    const float4 hn = *reinterpret_cast<const float4*>(q + 512 + j);
    const float4 hh = *reinterpret_cast<const float4*>(h0 + (long long)b * 256 + j);

    float4 r;
    { const float rr = sigf(ir01.x + hr.x), zz = sigf(iz01.x + hz.x);
      r.x = (1.f - zz) * tanhf(in01.x + rr * hn.x) + zz * hh.x; }
    { const float rr = sigf(ir01.y + hr.y), zz = sigf(iz01.y + hz.y);
      r.y = (1.f - zz) * tanhf(in01.y + rr * hn.y) + zz * hh.y; }
    { const float rr = sigf(ir23.x + hr.z), zz = sigf(iz23.x + hz.z);
      r.z = (1.f - zz) * tanhf(in23.x + rr * hn.z) + zz * hh.z; }
    { const float rr = sigf(ir23.y + hr.w), zz = sigf(iz23.y + hz.w);
      r.w = (1.f - zz) * tanhf(in23.y + rr * hn.w) + zz * hh.w; }

    const long long off = z * hoZ + (long long)b * 256 + j;
    *reinterpret_cast<float4*>(hout + off) = r;
    reinterpret_cast<__half2*>(h16 + off)[0] = __floats2half2_rn(r.x, r.y);
    reinterpret_cast<__half2*>(h16 + off)[1] = __floats2half2_rn(r.z, r.w);
}

// ---------------------------------------------------------------------------
__global__ void assemble_y_kernel(const float* __restrict__ o1, const float* __restrict__ o2,
                                  const int* __restrict__ cmap, float* __restrict__ y, int n4)
{
    const int idx = blockIdx.x * blockDim.x + threadIdx.x;   // over B*1024
    if (idx >= n4) return;
    const int b   = idx >> 10;
    const int rem = idx & 1023;
    const int i   = rem >> 4;
    const int j0  = (rem & 15) * 4;
    const float v = __ldg(&o1[b * 64 + i]);
    float4 r = make_float4(v, v, v, v);
    const int k = cmap[(i >> 3) * 8 + (j0 >> 3)];
    if (k >= 0) {
        const int t = (i & 7) * 8 + (j0 & 7);
        const float4 a = *reinterpret_cast<const float4*>(o2 + ((long long)k * BSZ + b) * 64 + t);
        r.x += a.x; r.y += a.y; r.z += a.z; r.w += a.w;
    }
    *reinterpret_cast<float4*>(y + (long long)idx * 4) = r;
}

// ---------------------------------------------------------------------------
extern "C" void kernel_launch(void* const* d_in, const int* in_sizes, int n_in,
                              void* d_out, int out_size)
{
    const float* x    = (const float*)d_in[0];
    const float* h    = (const float*)d_in[1];
    const float* fa   = (const float*)d_in[2];
    const float* e1w  = (const float*)d_in[3];
    const float* e1b  = (const float*)d_in[4];
    const float* wih1 = (const float*)d_in[5];
    const float* whh1 = (const float*)d_in[6];
    const float* bih1 = (const float*)d_in[7];
    const float* bhh1 = (const float*)d_in[8];
    const float* o1w  = (const float*)d_in[9];
    const float* o1b  = (const float*)d_in[10];
    const float* e2w  = (const float*)d_in[11];
    const float* e2b  = (const float*)d_in[12];
    const float* wih2 = (const float*)d_in[13];
    const float* whh2 = (const float*)d_in[14];
    const float* bih2 = (const float*)d_in[15];
    const float* bhh2 = (const float*)d_in[16];
    const float* o2w  = (const float*)d_in[17];
    const float* o2b  = (const float*)d_in[18];
    float* out = (float*)d_out;

    const int B = in_sizes[0] / 4096;                  // 2048
    const long long YOFF = (long long)B * 4096;
    int Kc = (int)(((long long)out_size - YOFF) / ((long long)B * 256)) - 1;
    if (Kc < 0) Kc = 0;
    if (Kc > MAXK) Kc = MAXK;

    __half *p_xh, *p_hh, *p_e1h, *p_wi1h, *p_whhh, *p_o1wh, *p_o2wh,
           *p_x1h, *p_gi1h, *p_gi2h, *p_hh16, *p_w2ph;
    float *p_bhh, *p_xp, *p_gh12, *p_o, *p_b2p;
    int *p_cx, *p_cy, *p_cmap;
    cudaGetSymbolAddress((void**)&p_xh,   d_xh);
    cudaGetSymbolAddress((void**)&p_hh,   d_hh);
    cudaGetSymbolAddress((void**)&p_e1h,  d_e1h);
    cudaGetSymbolAddress((void**)&p_wi1h, d_wi1h);
    cudaGetSymbolAddress((void**)&p_whhh, d_whhh);
    cudaGetSymbolAddress((void**)&p_bhh,  d_bhh);
    cudaGetSymbolAddress((void**)&p_o1wh, d_o1wh);
    cudaGetSymbolAddress((void**)&p_o2wh, d_o2wh);
    cudaGetSymbolAddress((void**)&p_xp,   d_xp);
    cudaGetSymbolAddress((void**)&p_x1h,  d_x1h);
    cudaGetSymbolAddress((void**)&p_gh12, d_gh12);
    cudaGetSymbolAddress((void**)&p_gi1h, d_gi1h);
    cudaGetSymbolAddress((void**)&p_gi2h, d_gi2h);
    cudaGetSymbolAddress((void**)&p_hh16, d_hh16);
    cudaGetSymbolAddress((void**)&p_o,    d_o);
    cudaGetSymbolAddress((void**)&p_w2ph, d_w2ph);
    cudaGetSymbolAddress((void**)&p_b2p,  d_b2p);
    cudaGetSymbolAddress((void**)&p_cx,   d_cx);
    cudaGetSymbolAddress((void**)&p_cy,   d_cy);
    cudaGetSymbolAddress((void**)&p_cmap, d_cmap);

    const int SMB128 = 2 * CAS * (128 * ROWH + 128 * ROWH);  // 61440 B
    const int SMB64  = 2 * CAS * (128 * ROWH + 64 * ROWH);   // 46080 B
    cudaFuncSetAttribute((const void*)gemm_hf<0, 128, 0, 0>, cudaFuncAttributeMaxDynamicSharedMemorySize, SMB128);
    cudaFuncSetAttribute((const void*)gemm_hf<0, 128, 1, 0>, cudaFuncAttributeMaxDynamicSharedMemorySize, SMB128);
    cudaFuncSetAttribute((const void*)gemm_hf<1, 128, 1, 0>, cudaFuncAttributeMaxDynamicSharedMemorySize, SMB128);
    cudaFuncSetAttribute((const void*)gemm_hf<0, 64, 0, 1>,  cudaFuncAttributeMaxDynamicSharedMemorySize, SMB64);

    float* yh0 = out + YOFF;
    float* yh2 = out + YOFF + (long long)B * 256;

    find_cells_kernel<<<1, 32>>>(fa, p_cx, p_cy, p_cmap);
    compose_w2_kernel<<<768, 64>>>(wih2, e2w, e2b, bih2, p_w2ph, p_b2p);

    // fp16 operand copies
    cvt_f16_kernel<<<(B * 1024 + 255) / 256, 256>>>(x, p_xh, B * 1024);
    cvt_f16_kernel<<<(B * 64 + 255) / 256, 256>>>(h, p_hh, B * 64);
    cvt_f16_kernel<<<(256 * 1024 + 255) / 256, 256>>>(e1w, p_e1h, 256 * 1024);
    cvt_f16_kernel<<<(768 * 64 + 255) / 256, 256>>>(wih1, p_wi1h, 768 * 64);
    cvt_f16_kernel<<<(64 * 64 + 255) / 256, 256>>>(o1w, p_o1wh, 64 * 64);
    cvt_f16_kernel<<<(64 * 64 + 255) / 256, 256>>>(o2w, p_o2wh, 64 * 64);
    concat_whh_kernel<<<(1536 * 64 + 255) / 256, 256>>>(whh1, whh2, bhh1, bhh2, p_whhh, p_bhh);

    // x1 split-K=4 partials (N=256, K slab=1024) + reduce -> fp16 x1
    gemm_hf<0, 128, 0, 0><<<dim3(2, B / 128, 4), 256, SMB128>>>(
        p_xh, p_e1h, nullptr, nullptr, nullptr, p_xp,
        256, 1024, 4096, 4096, 1024, 1024, (long long)B * 256, nullptr, nullptr);
    reduce_x1_kernel<<<(B * 64 + 255) / 256, 256>>>(p_xp, e1b, p_x1h, B * 64);

    // gh12 = h @ [whh1;whh2]^T + [bhh1;bhh2]  (N=1536, K=256) -> fp32
    gemm_hf<0, 128, 0, 0><<<dim3(12, B / 128), 256, SMB128>>>(
        p_hh, p_whhh, nullptr, p_bhh, nullptr, p_gh12,
        1536, 256, 256, 256, 0, 0, 0, nullptr, nullptr);

    // gi1 = x1 @ wih1^T + bih1 -> fp16  (N=768, K=256)
    gemm_hf<0, 128, 1, 0><<<dim3(6, B / 128), 256, SMB128>>>(
        p_x1h, p_wi1h, nullptr, bih1, nullptr, p_gi1h,
        768, 256, 256, 256, 0, 0, 0, nullptr, nullptr);

    // h1 -> out y_h[0] + fp16 slot 0
    gru_elem_h_kernel<<<dim3((B * 64 + 255) / 256, 1, 1), 256>>>(
        p_gi1h, p_gh12, h, yh0, p_hh16, B * 64, 0, 0, 1536);

    if (Kc > 0) {
        // gi2[k] = patch[k] @ W2p^T + b2p -> fp16  (gather A; N=768, K=64)
        gemm_hf<1, 128, 1, 0><<<dim3(6, B / 128, Kc), 256, SMB128>>>(
            p_xh, p_w2ph, nullptr, p_b2p, nullptr, p_gi2h,
            768, 64, 64, 64, 0, 0, (long long)B * 768, p_cx, p_cy);
        // h2[k] -> out y_h[1+k] + fp16 slots 1..Kc
        gru_elem_h_kernel<<<dim3((B * 64 + 255) / 256, 1, Kc), 256>>>(
            p_gi2h, p_gh12 + 768, h, yh2, p_hh16 + (long long)B * 256,
            B * 64, (long long)B * 768, (long long)B * 256, 1536);
    }

    // merged o GEMM: A = fp16 h slots; z=0 -> o1w, z>0 -> o2w
    gemm_hf<0, 64, 0, 1><<<dim3(1, B / 128, Kc + 1), 256, SMB64>>>(
        p_hh16, p_o1wh, p_o2wh, o1b, o2b, p_o,
        64, 256, 256, 256, (long long)B * 256, 0, (long long)B * 64, nullptr, nullptr);

    // y = bcast(o1) + scatter(o2)
    assemble_y_kernel<<<(B * 1024 + 255) / 256, 256>>>(p_o, p_o + (long long)B * 64,
                                                       p_cmap, out, B * 1024);
}

// round 9
// speedup vs baseline: 1.5566x; 1.1063x over previous
#include <cuda_runtime.h>
#include <cuda_fp16.h>
#include <cstdint>

// ---------------------------------------------------------------------------
// FocDecoderRNN — fp16 tensor-core engine + horizontally-fused launch graph.
//   prep_kernel : all cvts + concat + compose_w2 + find_cells  (1 launch)
//   big_fused   : x1-splitK ∥ gh12 ∥ gi2(all cells)            (1 launch)
//   then: reduce -> gi1 -> gru(all z) -> merged o -> assemble
// ---------------------------------------------------------------------------

#define BSZ  2048
#define MAXK 64

__device__ __half d_xh  [(size_t)BSZ * 4096];
__device__ __half d_hh  [BSZ * 256];
__device__ __half d_e1h [256 * 4096];
__device__ __half d_wi1h[768 * 256];
__device__ __half d_whhh[1536 * 256];
__device__ float  d_bhh [1536];
__device__ __half d_o1wh[64 * 256];
__device__ __half d_o2wh[64 * 256];
__device__ float  d_xp  [4 * BSZ * 256];
__device__ __half d_x1h [BSZ * 256];
__device__ float  d_gh12[(size_t)BSZ * 1536];
__device__ __half d_gi1h[BSZ * 768];
__device__ __half d_gi2h[(size_t)MAXK * BSZ * 768];
__device__ __half d_hh16[(size_t)(MAXK + 1) * BSZ * 256];
__device__ float  d_o   [(size_t)(MAXK + 1) * BSZ * 64];
__device__ __half d_w2ph[768 * 64];
__device__ float  d_b2p [768];
__device__ int    d_cx[MAXK], d_cy[MAXK], d_cmap[64];

// ---------------------------------------------------------------------------
__device__ __forceinline__ void mma_f16(float c[4], const uint32_t a[4], const uint32_t b[2])
{
    asm volatile(
        "mma.sync.aligned.m16n8k16.row.col.f32.f16.f16.f32 "
        "{%0,%1,%2,%3},{%4,%5,%6,%7},{%8,%9},{%0,%1,%2,%3};\n"
        : "+f"(c[0]), "+f"(c[1]), "+f"(c[2]), "+f"(c[3])
        : "r"(a[0]), "r"(a[1]), "r"(a[2]), "r"(a[3]), "r"(b[0]), "r"(b[1]));
}

__device__ __forceinline__ void cp16(uint32_t smem_addr, const void* gptr)
{
    asm volatile("cp.async.cg.shared.global [%0], [%1], 16;"
                 :: "r"(smem_addr), "l"(gptr));
}

__device__ __forceinline__ float sigf(float x) { return 1.f / (1.f + __expf(-x)); }

// ---------------------------------------------------------------------------
// PREP: all independent small jobs in one launch (256-thread blocks).
__device__ __forceinline__ void cvt_job(const float* __restrict__ s, __half* __restrict__ d,
                                        int grp)
{
    const float4 v = reinterpret_cast<const float4*>(s)[grp];
    reinterpret_cast<__half2*>(d)[grp * 2]     = __floats2half2_rn(v.x, v.y);
    reinterpret_cast<__half2*>(d)[grp * 2 + 1] = __floats2half2_rn(v.z, v.w);
}

__global__ void prep_kernel(const float* __restrict__ x,   const float* __restrict__ h,
                            const float* __restrict__ e1w, const float* __restrict__ wih1,
                            const float* __restrict__ o1w, const float* __restrict__ o2w,
                            const float* __restrict__ whh1, const float* __restrict__ whh2,
                            const float* __restrict__ bhh1, const float* __restrict__ bhh2,
                            const float* __restrict__ wih2, const float* __restrict__ e2w,
                            const float* __restrict__ e2b,  const float* __restrict__ bih2,
                            const float* __restrict__ fa,
                            __half* __restrict__ xh,  __half* __restrict__ hh,
                            __half* __restrict__ e1h, __half* __restrict__ wi1h,
                            __half* __restrict__ o1wh, __half* __restrict__ o2wh,
                            __half* __restrict__ whhh, float* __restrict__ bhh,
                            __half* __restrict__ w2ph, float* __restrict__ b2p,
                            int* __restrict__ cx, int* __restrict__ cy, int* __restrict__ cmap,
                            int B)
{
    const int bid = blockIdx.x;
    const int tid = threadIdx.x;
    const int b0 = B * 4;                 // xh groups /256
    const int b1 = b0 + B / 4;            // hh
    const int b2 = b1 + 1024;             // e1h
    const int b3 = b2 + 192;              // wi1h
    const int b4 = b3 + 16;               // o1wh
    const int b5 = b4 + 16;               // o2wh
    const int b6 = b5 + 384;              // whh concat
    const int b7 = b6 + 192;              // compose w2
                                          // b7: find_cells (1 block)
    if (bid < b0)      { cvt_job(x,    xh,   bid * 256 + tid); }
    else if (bid < b1) { cvt_job(h,    hh,   (bid - b0) * 256 + tid); }
    else if (bid < b2) { cvt_job(e1w,  e1h,  (bid - b1) * 256 + tid); }
    else if (bid < b3) { cvt_job(wih1, wi1h, (bid - b2) * 256 + tid); }
    else if (bid < b4) { cvt_job(o1w,  o1wh, (bid - b3) * 256 + tid); }
    else if (bid < b5) { cvt_job(o2w,  o2wh, (bid - b4) * 256 + tid); }
    else if (bid < b6) {
        const int i = (bid - b5) * 256 + tid;         // over 1536*64
        const int e = i * 4, row = e >> 8, col = e & 255;
        const float* src = (row < 768) ? (whh1 + row * 256 + col)
                                       : (whh2 + (row - 768) * 256 + col);
        const float4 v = *reinterpret_cast<const float4*>(src);
        reinterpret_cast<__half2*>(whhh)[i * 2]     = __floats2half2_rn(v.x, v.y);
        reinterpret_cast<__half2*>(whhh)[i * 2 + 1] = __floats2half2_rn(v.z, v.w);
        if (i < 1536) bhh[i] = (i < 768) ? bhh1[i] : bhh2[i - 768];
    } else if (bid < b7) {
        const int n = (bid - b6) * 4 + (tid >> 6);    // 0..767
        const int t = tid & 63;
        float s = 0.f;
        for (int c = 0; c < 256; c++)
            s += wih2[n * 256 + c] * e2w[c * 64 + t];
        w2ph[n * 64 + t] = __float2half_rn(s);
        if (t == 0) {
            float sb = 0.f;
            for (int c = 0; c < 256; c++) sb += wih2[n * 256 + c] * e2b[c];
            b2p[n] = bih2[n] + sb;
        }
    } else {
        if (tid == 0) {
            for (int i = 0; i < 64; i++) cmap[i] = -1;
            int k = 0;
            for (int i = 0; i < 8; i++)
                for (int j = 0; j < 8; j++)
                    if (fa[i * 8 + j] > 0.5f) { cx[k] = i; cy[k] = j; cmap[i * 8 + j] = k; k++; }
        }
    }
}

// ---------------------------------------------------------------------------
// FP16 GEMM-NT device core (cp.async 3-stage, K-slab 32, m16n8k16).
#define CAS  3
#define ROWH 40

template<int AMODE, int NT, int HOUT>
__device__ __forceinline__
void gemm_dev(const __half* __restrict__ A, const __half* __restrict__ Bw,
              const float* __restrict__ bias, void* __restrict__ Cv,
              int N, int K, int lda, int ldb,
              long long sAz, long long sBz, long long sCz,
              const int* __restrict__ cxs, const int* __restrict__ cys,
              int bx, int by, int bz)
{
    constexpr int STG_A = 128 * ROWH;
    constexpr int STG_B = NT * ROWH;
    constexpr int WNW   = (NT == 128) ? 4 : 2;
    constexpr int MF    = (NT == 128) ? 4 : 2;

    extern __shared__ __half smh[];
    const uint32_t smBase = (uint32_t)__cvta_generic_to_shared(smh);

    const int bm = by * 128;
    const int bn = bx * NT;
    int cellBase = 0;
    if (AMODE == 1) cellBase = cxs[bz] * 512 + cys[bz] * 8;
    if (AMODE == 0) A += (long long)bz * sAz;
    Bw += (long long)bz * sBz;

    const int tid  = threadIdx.x;
    const int lane = tid & 31;
    const int wid  = tid >> 5;
    const int wm   = wid / WNW;
    const int wn   = wid % WNW;
    const int g    = lane >> 2;
    const int t2   = (lane & 3) * 2;
    const int lr   = tid >> 1;
    const int lk   = (tid & 1) * 16;
    const int br   = (NT == 128) ? (tid >> 1) : (tid >> 2);
    const int bc   = (NT == 128) ? (tid & 1) * 16 : (tid & 3) * 8;

    float acc[MF][4][4];
#pragma unroll
    for (int i = 0; i < MF; i++)
#pragma unroll
        for (int j = 0; j < 4; j++)
#pragma unroll
            for (int q = 0; q < 4; q++) acc[i][j][q] = 0.f;

    auto issue = [&](int stg, int k0) {
        const __half *ap0, *ap1;
        if (AMODE == 0) {
            ap0 = A + (long long)(bm + lr) * lda + k0 + lk;
            ap1 = ap0 + 8;
        } else {
            const int tt = k0 + lk;
            const __half* base = A + (long long)(bm + lr) * 4096 + cellBase;
            ap0 = base + ((tt >> 3) << 6);
            ap1 = base + (((tt + 8) >> 3) << 6);
        }
        const uint32_t da = smBase + 2u * (stg * STG_A + lr * ROWH + lk);
        cp16(da,      ap0);
        cp16(da + 16, ap1);
        const __half* bp = Bw + (long long)(bn + br) * ldb + k0 + bc;
        const uint32_t db = smBase + 2u * (CAS * STG_A + stg * STG_B + br * ROWH + bc);
        cp16(db, bp);
        if (NT == 128) cp16(db + 16, bp + 8);
    };

    const int nIter = K >> 5;
#pragma unroll
    for (int s = 0; s < CAS - 1; s++) {
        if (s < nIter) issue(s, s * 32);
        asm volatile("cp.async.commit_group;");
    }

    for (int it = 0; it < nIter; it++) {
        const int cur = it % CAS;
        asm volatile("cp.async.wait_group %0;" :: "n"(CAS - 2));
        __syncthreads();

        const __half* Ab = smh + cur * STG_A;
        const __half* Bb = smh + CAS * STG_A + cur * STG_B;
#pragma unroll
        for (int kk = 0; kk < 32; kk += 16) {
            uint32_t af[MF][4], bf[4][2];
#pragma unroll
            for (int i = 0; i < MF; i++) {
                const int m = wm * (MF * 16) + i * 16;
                af[i][0] = *reinterpret_cast<const uint32_t*>(Ab + (m + g) * ROWH + kk + t2);
                af[i][1] = *reinterpret_cast<const uint32_t*>(Ab + (m + 8 + g) * ROWH + kk + t2);
                af[i][2] = *reinterpret_cast<const uint32_t*>(Ab + (m + g) * ROWH + kk + t2 + 8);
                af[i][3] = *reinterpret_cast<const uint32_t*>(Ab + (m + 8 + g) * ROWH + kk + t2 + 8);
            }
#pragma unroll
            for (int j = 0; j < 4; j++) {
                const int n = wn * 32 + j * 8;
                bf[j][0] = *reinterpret_cast<const uint32_t*>(Bb + (n + g) * ROWH + kk + t2);
                bf[j][1] = *reinterpret_cast<const uint32_t*>(Bb + (n + g) * ROWH + kk + t2 + 8);
            }
#pragma unroll
            for (int i = 0; i < MF; i++)
#pragma unroll
                for (int j = 0; j < 4; j++) mma_f16(acc[i][j], af[i], bf[j]);
        }
        const int nk = it + CAS - 1;
        if (nk < nIter) issue(nk % CAS, nk * 32);
        asm volatile("cp.async.commit_group;");
    }

    float* Cf = (float*)Cv;
    __half* Ch = (__half*)Cv;
#pragma unroll
    for (int i = 0; i < MF; i++) {
        const int row0 = bm + wm * (MF * 16) + i * 16 + g;
#pragma unroll
        for (int j = 0; j < 4; j++) {
            const int col = bn + wn * 32 + j * 8 + t2;
            float bz0 = 0.f, bz1 = 0.f;
            if (bias) { bz0 = __ldg(&bias[col]); bz1 = __ldg(&bias[col + 1]); }
            const float v0 = acc[i][j][0] + bz0, v1 = acc[i][j][1] + bz1;
            const float v2 = acc[i][j][2] + bz0, v3 = acc[i][j][3] + bz1;
            if (HOUT == 0) {
                float* C = Cf + (long long)bz * sCz;
                *reinterpret_cast<float2*>(&C[(long long)row0 * N + col]) = make_float2(v0, v1);
                *reinterpret_cast<float2*>(&C[(long long)(row0 + 8) * N + col]) = make_float2(v2, v3);
            } else {
                __half* C = Ch + (long long)bz * sCz;
                *reinterpret_cast<__half2*>(&C[(long long)row0 * N + col]) =
                    __floats2half2_rn(v0, v1);
                *reinterpret_cast<__half2*>(&C[(long long)(row0 + 8) * N + col]) =
                    __floats2half2_rn(v2, v3);
            }
        }
    }
}

// ---------------------------------------------------------------------------
// big_fused: 1D decode -> x1-splitK | gh12 | gi2(all cells).
//   [0, nX1)          x1 partials: bx=i%2, by=(i/2)%MB, bz=i/(2*MB)   K=1024
//   [nX1, nX1+nGH)    gh12:        j=i-nX1, bx=j%12, by=j/12          K=256
//   [.., +nGI2)       gi2:         k=.., bx=k%6, by=(k/6)%MB, bz=k/(6*MB) K=64
__global__ __launch_bounds__(256)
void big_fused(const __half* __restrict__ xh, const __half* __restrict__ e1h,
               const __half* __restrict__ hh, const __half* __restrict__ whhh,
               const float* __restrict__ bhh, const __half* __restrict__ w2ph,
               const float* __restrict__ b2p,
               float* __restrict__ xp, float* __restrict__ gh12,
               __half* __restrict__ gi2h,
               const int* __restrict__ cxs, const int* __restrict__ cys,
               int MB, int nX1, int nGH, int B)
{
    const int i = blockIdx.x;
    if (i < nX1) {
        const int bx = i & 1, r = i >> 1;
        gemm_dev<0, 128, 0>(xh, e1h, nullptr, xp, 256, 1024, 4096, 4096,
                            1024, 1024, (long long)B * 256, nullptr, nullptr,
                            bx, r % MB, r / MB);
    } else if (i < nX1 + nGH) {
        const int j = i - nX1;
        gemm_dev<0, 128, 0>(hh, whhh, bhh, gh12, 1536, 256, 256, 256,
                            0, 0, 0, nullptr, nullptr,
                            j % 12, j / 12, 0);
    } else {
        const int k = i - nX1 - nGH;
        const int bx = k % 6, r = k / 6;
        gemm_dev<1, 128, 1>(xh, w2ph, b2p, gi2h, 768, 64, 64, 64,
                            0, 0, (long long)B * 768, cxs, cys,
                            bx, r % MB, r / MB);
    }
}

// standalone GEMMs (gi1, merged o)
template<int NT, int OSEL>
__global__ __launch_bounds__(256)
void gemm_hf(const __half* __restrict__ A,
             const __half* __restrict__ Bw, const __half* __restrict__ Bw2,
             const float* __restrict__ bias, const float* __restrict__ bias2,
             void* __restrict__ Cv,
             int N, int K, int lda, int ldb,
             long long sAz, long long sBz, long long sCz,
             int HOUTv)
{
    const __half* B_ = (OSEL == 1 && blockIdx.z > 0) ? Bw2 : Bw;
    const float* bi  = (OSEL == 1 && blockIdx.z > 0) ? bias2 : bias;
    if (HOUTv == 0)
        gemm_dev<0, NT, 0>(A, B_, bi, Cv, N, K, lda, ldb, sAz, sBz, sCz,
                           nullptr, nullptr, blockIdx.x, blockIdx.y, blockIdx.z);
    else
        gemm_dev<0, NT, 1>(A, B_, bi, Cv, N, K, lda, ldb, sAz, sBz, sCz,
                           nullptr, nullptr, blockIdx.x, blockIdx.y, blockIdx.z);
}

// ---------------------------------------------------------------------------
__global__ void reduce_x1_kernel(const float* __restrict__ P, const float* __restrict__ bias,
                                 __half* __restrict__ x1, int n4)
{
    const int idx = blockIdx.x * blockDim.x + threadIdx.x;
    if (idx >= n4) return;
    const float4 p0 = *reinterpret_cast<const float4*>(P + (size_t)0 * BSZ * 256 + idx * 4);
    const float4 p1 = *reinterpret_cast<const float4*>(P + (size_t)1 * BSZ * 256 + idx * 4);
    const float4 p2 = *reinterpret_cast<const float4*>(P + (size_t)2 * BSZ * 256 + idx * 4);
    const float4 p3 = *reinterpret_cast<const float4*>(P + (size_t)3 * BSZ * 256 + idx * 4);
    const int j0 = (idx * 4) & 255;
    const float4 b = *reinterpret_cast<const float4*>(bias + j0);
    reinterpret_cast<__half2*>(x1)[idx * 2] =
        __floats2half2_rn(p0.x + p1.x + p2.x + p3.x + b.x,
                          p0.y + p1.y + p2.y + p3.y + b.y);
    reinterpret_cast<__half2*>(x1)[idx * 2 + 1] =
        __floats2half2_rn(p0.z + p1.z + p2.z + p3.z + b.z,
                          p0.w + p1.w + p2.w + p3.w + b.w);
}

// ---------------------------------------------------------------------------
// merged GRU: z=0 -> gi1/gh12[0:768]; z>0 -> gi2[z-1]/gh12[768:1536].
__global__ void gru_all_kernel(const __half* __restrict__ gi1, const __half* __restrict__ gi2,
                               const float* __restrict__ gh12, const float* __restrict__ h0,
                               float* __restrict__ hout, __half* __restrict__ h16,
                               int n4, long long Bll)
{
    const long long z = blockIdx.z;
    const int idx = blockIdx.x * blockDim.x + threadIdx.x;   // over B*64
    if (idx >= n4) return;
    const int b = idx >> 6;
    const int j = (idx & 63) * 4;
    const __half* g = (z == 0) ? (gi1 + (long long)b * 768)
                               : (gi2 + ((z - 1) * Bll + b) * 768);
    const float* q = gh12 + (long long)b * 1536 + (z ? 768 : 0);

    const float2 ir01 = __half22float2(*reinterpret_cast<const __half2*>(g + j));
    const float2 ir23 = __half22float2(*reinterpret_cast<const __half2*>(g + j + 2));
    const float2 iz01 = __half22float2(*reinterpret_cast<const __half2*>(g + 256 + j));
    const float2 iz23 = __half22float2(*reinterpret_cast<const __half2*>(g + 256 + j + 2));
    const float2 in01 = __half22float2(*reinterpret_cast<const __half2*>(g + 512 + j));
    const float2 in23 = __half22float2(*reinterpret_cast<const __half2*>(g + 512 + j + 2));
    const float4 hr = *reinterpret_cast<const float4*>(q + j);
    const float4 hz = *reinterpret_cast<const float4*>(q + 256 + j);
    const float4 hn = *reinterpret_cast<const float4*>(q + 512 + j);
    const float4 hh = *reinterpret_cast<const float4*>(h0 + (long long)b * 256 + j);

    float4 r;
    { const float rr = sigf(ir01.x + hr.x), zz = sigf(iz01.x + hz.x);
      r.x = (1.f - zz) * tanhf(in01.x + rr * hn.x) + zz * hh.x; }
    { const float rr = sigf(ir01.y + hr.y), zz = sigf(iz01.y + hz.y);
      r.y = (1.f - zz) * tanhf(in01.y + rr * hn.y) + zz * hh.y; }
    { const float rr = sigf(ir23.x + hr.z), zz = sigf(iz23.x + hz.z);
      r.z = (1.f - zz) * tanhf(in23.x + rr * hn.z) + zz * hh.z; }
    { const float rr = sigf(ir23.y + hr.w), zz = sigf(iz23.y + hz.w);
      r.w = (1.f - zz) * tanhf(in23.y + rr * hn.w) + zz * hh.w; }

    const long long off = z * (Bll * 256) + (long long)b * 256 + j;
    *reinterpret_cast<float4*>(hout + off) = r;
    reinterpret_cast<__half2*>(h16 + off)[0] = __floats2half2_rn(r.x, r.y);
    reinterpret_cast<__half2*>(h16 + off)[1] = __floats2half2_rn(r.z, r.w);
}

// ---------------------------------------------------------------------------
__global__ void assemble_y_kernel(const float* __restrict__ o1, const float* __restrict__ o2,
                                  const int* __restrict__ cmap, float* __restrict__ y, int n4)
{
    const int idx = blockIdx.x * blockDim.x + threadIdx.x;   // over B*1024
    if (idx >= n4) return;
    const int b   = idx >> 10;
    const int rem = idx & 1023;
    const int i   = rem >> 4;
    const int j0  = (rem & 15) * 4;
    const float v = __ldg(&o1[b * 64 + i]);
    float4 r = make_float4(v, v, v, v);
    const int k = cmap[(i >> 3) * 8 + (j0 >> 3)];
    if (k >= 0) {
        const int t = (i & 7) * 8 + (j0 & 7);
        const float4 a = *reinterpret_cast<const float4*>(o2 + ((long long)k * BSZ + b) * 64 + t);
        r.x += a.x; r.y += a.y; r.z += a.z; r.w += a.w;
    }
    *reinterpret_cast<float4*>(y + (long long)idx * 4) = r;
}

// ---------------------------------------------------------------------------
extern "C" void kernel_launch(void* const* d_in, const int* in_sizes, int n_in,
                              void* d_out, int out_size)
{
    const float* x    = (const float*)d_in[0];
    const float* h    = (const float*)d_in[1];
    const float* fa   = (const float*)d_in[2];
    const float* e1w  = (const float*)d_in[3];
    const float* e1b  = (const float*)d_in[4];
    const float* wih1 = (const float*)d_in[5];
    const float* whh1 = (const float*)d_in[6];
    const float* bih1 = (const float*)d_in[7];
    const float* bhh1 = (const float*)d_in[8];
    const float* o1w  = (const float*)d_in[9];
    const float* o1b  = (const float*)d_in[10];
    const float* e2w  = (const float*)d_in[11];
    const float* e2b  = (const float*)d_in[12];
    const float* wih2 = (const float*)d_in[13];
    const float* whh2 = (const float*)d_in[14];
    const float* bih2 = (const float*)d_in[15];
    const float* bhh2 = (const float*)d_in[16];
    const float* o2w  = (const float*)d_in[17];
    const float* o2b  = (const float*)d_in[18];
    float* out = (float*)d_out;

    const int B = in_sizes[0] / 4096;                  // 2048
    const long long YOFF = (long long)B * 4096;
    int Kc = (int)(((long long)out_size - YOFF) / ((long long)B * 256)) - 1;
    if (Kc < 0) Kc = 0;
    if (Kc > MAXK) Kc = MAXK;

    __half *p_xh, *p_hh, *p_e1h, *p_wi1h, *p_whhh, *p_o1wh, *p_o2wh,
           *p_x1h, *p_gi1h, *p_gi2h, *p_hh16, *p_w2ph;
    float *p_bhh, *p_xp, *p_gh12, *p_o, *p_b2p;
    int *p_cx, *p_cy, *p_cmap;
    cudaGetSymbolAddress((void**)&p_xh,   d_xh);
    cudaGetSymbolAddress((void**)&p_hh,   d_hh);
    cudaGetSymbolAddress((void**)&p_e1h,  d_e1h);
    cudaGetSymbolAddress((void**)&p_wi1h, d_wi1h);
    cudaGetSymbolAddress((void**)&p_whhh, d_whhh);
    cudaGetSymbolAddress((void**)&p_bhh,  d_bhh);
    cudaGetSymbolAddress((void**)&p_o1wh, d_o1wh);
    cudaGetSymbolAddress((void**)&p_o2wh, d_o2wh);
    cudaGetSymbolAddress((void**)&p_xp,   d_xp);
    cudaGetSymbolAddress((void**)&p_x1h,  d_x1h);
    cudaGetSymbolAddress((void**)&p_gh12, d_gh12);
    cudaGetSymbolAddress((void**)&p_gi1h, d_gi1h);
    cudaGetSymbolAddress((void**)&p_gi2h, d_gi2h);
    cudaGetSymbolAddress((void**)&p_hh16, d_hh16);
    cudaGetSymbolAddress((void**)&p_o,    d_o);
    cudaGetSymbolAddress((void**)&p_w2ph, d_w2ph);
    cudaGetSymbolAddress((void**)&p_b2p,  d_b2p);
    cudaGetSymbolAddress((void**)&p_cx,   d_cx);
    cudaGetSymbolAddress((void**)&p_cy,   d_cy);
    cudaGetSymbolAddress((void**)&p_cmap, d_cmap);

    const int SMB128 = 2 * CAS * (128 * ROWH + 128 * ROWH);  // 61440 B
    const int SMB64  = 2 * CAS * (128 * ROWH + 64 * ROWH);   // 46080 B
    cudaFuncSetAttribute((const void*)big_fused,      cudaFuncAttributeMaxDynamicSharedMemorySize, SMB128);
    cudaFuncSetAttribute((const void*)gemm_hf<128, 0>, cudaFuncAttributeMaxDynamicSharedMemorySize, SMB128);
    cudaFuncSetAttribute((const void*)gemm_hf<64, 1>,  cudaFuncAttributeMaxDynamicSharedMemorySize, SMB64);

    float* yh0 = out + YOFF;

    const int MB = B / 128;                       // 16
    const int nPrep = B * 4 + B / 4 + 1024 + 192 + 16 + 16 + 384 + 192 + 1;

    // 1) all prep in one launch
    prep_kernel<<<nPrep, 256>>>(x, h, e1w, wih1, o1w, o2w, whh1, whh2, bhh1, bhh2,
                                wih2, e2w, e2b, bih2, fa,
                                p_xh, p_hh, p_e1h, p_wi1h, p_o1wh, p_o2wh,
                                p_whhh, p_bhh, p_w2ph, p_b2p,
                                p_cx, p_cy, p_cmap, B);

    // 2) x1-splitK + gh12 + gi2 (all cells) in one wide launch
    const int nX1  = 2 * MB * 4;
    const int nGH  = 12 * MB;
    const int nGI2 = 6 * MB * Kc;
    big_fused<<<nX1 + nGH + nGI2, 256, SMB128>>>(
        p_xh, p_e1h, p_hh, p_whhh, p_bhh, p_w2ph, p_b2p,
        p_xp, p_gh12, p_gi2h, p_cx, p_cy, MB, nX1, nGH, B);

    // 3) reduce -> fp16 x1
    reduce_x1_kernel<<<(B * 64 + 255) / 256, 256>>>(p_xp, e1b, p_x1h, B * 64);

    // 4) gi1 = x1 @ wih1^T + bih1 -> fp16
    gemm_hf<128, 0><<<dim3(6, MB), 256, SMB128>>>(
        p_x1h, p_wi1h, nullptr, bih1, nullptr, p_gi1h,
        768, 256, 256, 256, 0, 0, 0, 1);

    // 5) all GRUs (z=0: layer1; z>0: cells) -> out h slots + fp16 slots
    gru_all_kernel<<<dim3((B * 64 + 255) / 256, 1, Kc + 1), 256>>>(
        p_gi1h, p_gi2h, p_gh12, h, yh0, p_hh16, B * 64, (long long)B);

    // 6) merged o GEMM: z=0 -> o1w, z>0 -> o2w
    gemm_hf<64, 1><<<dim3(1, MB, Kc + 1), 256, SMB64>>>(
        p_hh16, p_o1wh, p_o2wh, o1b, o2b, p_o,
        64, 256, 256, 256, (long long)B * 256, 0, (long long)B * 64, 0);

    // 7) y = bcast(o1) + scatter(o2)
    assemble_y_kernel<<<(B * 1024 + 255) / 256, 256>>>(p_o, p_o + (long long)B * 64,
                                                       p_cmap, out, B * 1024);
}